// round 1
// baseline (speedup 1.0000x reference)
#include <cuda_runtime.h>

#define NN 100000
#define NE 3200000
#define KF 1433
#define NH 16
#define NO 7

// ---------------- scratch (device globals; no allocation allowed) ----------
__device__ float g_deg_out[NN];               // becomes norm_src after norm_kernel
__device__ float g_deg_in[NN];                // becomes norm_dst after norm_kernel
__device__ __align__(16) float g_x1[NN * 16];
__device__ __align__(16) float g_m1[NN * 16];
__device__ __align__(16) float g_x2[NN * 8];
__device__ __align__(16) float g_m2[NN * 8];
__device__ int g_src[NE];
__device__ int g_dst[NE];
__device__ int g_is64;

// ---------------- small PTX helpers ----------------------------------------
__device__ __forceinline__ unsigned long long fma2(unsigned long long a,
                                                   unsigned long long b,
                                                   unsigned long long c) {
    unsigned long long d;
    asm("fma.rn.f32x2 %0, %1, %2, %3;" : "=l"(d) : "l"(a), "l"(b), "l"(c));
    return d;
}
__device__ __forceinline__ unsigned long long pack2(float x) {
    unsigned long long d;
    asm("mov.b64 %0, {%1, %1};" : "=l"(d) : "f"(x));
    return d;
}
__device__ __forceinline__ float2 unpack2(unsigned long long v) {
    float2 f;
    asm("mov.b64 {%0, %1}, %2;" : "=f"(f.x), "=f"(f.y) : "l"(v));
    return f;
}
__device__ __forceinline__ void red4(float* p, float4 v) {
    asm volatile("red.global.add.v4.f32 [%0], {%1, %2, %3, %4};"
                 :: "l"(p), "f"(v.x), "f"(v.y), "f"(v.z), "f"(v.w)
                 : "memory");
}

// ---------------- edge dtype detect + convert ------------------------------
// int64 edges: every odd 32-bit word (high half) is 0. int32 edges: odd words
// are random edge ids in [0, 100000) — all-32-zero has probability ~1e-160.
__global__ void detect_kernel(const void* ei) {
    const int* w = (const int*)ei;
    int t = threadIdx.x;
    int v = w[2 * t + 1];
    unsigned b = __ballot_sync(0xffffffffu, v != 0);
    if (t == 0) g_is64 = (b == 0) ? 1 : 0;
}

__global__ void convert_kernel(const void* ei) {
    int e = blockIdx.x * blockDim.x + threadIdx.x;
    if (e >= NE) return;
    if (g_is64) {
        const long long* p = (const long long*)ei;
        g_src[e] = (int)p[e];
        g_dst[e] = (int)p[NE + e];
    } else {
        const int* p = (const int*)ei;
        g_src[e] = p[e];
        g_dst[e] = p[NE + e];
    }
}

// ---------------- degrees + norms ------------------------------------------
__global__ void deg_kernel() {
    int e = blockIdx.x * blockDim.x + threadIdx.x;
    if (e >= NE) return;
    atomicAdd(&g_deg_out[g_src[e]], 1.0f);
    atomicAdd(&g_deg_in[g_dst[e]], 1.0f);
}

__global__ void norm_kernel() {
    int i = blockIdx.x * blockDim.x + threadIdx.x;
    if (i >= NN) return;
    g_deg_out[i] = rsqrtf(fmaxf(g_deg_out[i], 1.0f));
    g_deg_in[i]  = rsqrtf(fmaxf(g_deg_in[i], 1.0f));
}

// ---------------- GEMM1: x1 = (feat * norm_src) @ W1  [100k x 16] ----------
// Block tile: 256 nodes x 16 cols, k-chunks of 32.
// Thread (t): node pair nl0 = t & ~1 (2 nodes), col half ch = t & 1 (8 cols).
// Packed f32x2 FMAs (8 per k per thread). Register-prefetch double buffering.
__global__ void __launch_bounds__(256) gemm1_kernel(const float* __restrict__ feat,
                                                    const float* __restrict__ W1) {
    __shared__ float As[256][33];   // [node_local][k], pitch 33 -> conflict-free
    __shared__ float Ws[32][16];    // [k][col]

    const int tid  = threadIdx.x;
    const int wid  = tid >> 5;
    const int lane = tid & 31;
    const int node0 = blockIdx.x * 256;
    const int nl0 = tid & ~1;       // 0,2,...,254
    const int ch  = tid & 1;        // column half (8 cols)

    unsigned long long acc[2][4];
#pragma unroll
    for (int i = 0; i < 2; i++)
#pragma unroll
        for (int j = 0; j < 4; j++) acc[i][j] = 0ull;

    float r[32];
    float wr0, wr1;
    const int wrow0 = tid >> 4, wcol0 = tid & 15;          // Ws flat idx tid
    const int wrow1 = (tid + 256) >> 4, wcol1 = tid & 15;  // Ws flat idx tid+256

    // prologue: load chunk 0 into smem
    {
        const int k0 = 0;
#pragma unroll
        for (int t = 0; t < 32; t++) {
            int nl = t * 8 + wid;
            int ng = node0 + nl;
            int kk = k0 + lane;
            r[t] = (ng < NN && kk < KF) ? feat[(size_t)ng * KF + kk] : 0.0f;
        }
        wr0 = (k0 + wrow0 < KF) ? W1[(k0 + wrow0) * NH + wcol0] : 0.0f;
        wr1 = (k0 + wrow1 < KF) ? W1[(k0 + wrow1) * NH + wcol1] : 0.0f;
#pragma unroll
        for (int t = 0; t < 32; t++) As[t * 8 + wid][lane] = r[t];
        Ws[wrow0][wcol0] = wr0;
        Ws[wrow1][wcol1] = wr1;
    }
    __syncthreads();

    const int NCHUNK = (KF + 31) / 32;  // 45
    for (int c = 0; c < NCHUNK; c++) {
        const int k0n = (c + 1) * 32;
        const bool more = (k0n < KF);

        // prefetch next chunk into registers (hides LDG latency under compute)
        if (more) {
#pragma unroll
            for (int t = 0; t < 32; t++) {
                int nl = t * 8 + wid;
                int ng = node0 + nl;
                int kk = k0n + lane;
                r[t] = (ng < NN && kk < KF) ? feat[(size_t)ng * KF + kk] : 0.0f;
            }
            wr0 = (k0n + wrow0 < KF) ? W1[(k0n + wrow0) * NH + wcol0] : 0.0f;
            wr1 = (k0n + wrow1 < KF) ? W1[(k0n + wrow1) * NH + wcol1] : 0.0f;
        }

        // compute current chunk
#pragma unroll
        for (int k = 0; k < 32; k++) {
            float a0 = As[nl0][k];
            float a1 = As[nl0 + 1][k];
            const float* wp = &Ws[k][ch * 8];
            ulonglong2 wA = *(const ulonglong2*)wp;        // cols c0..c3 (2 pairs)
            ulonglong2 wB = *(const ulonglong2*)(wp + 4);  // cols c4..c7 (2 pairs)
            unsigned long long A0 = pack2(a0);
            unsigned long long A1 = pack2(a1);
            acc[0][0] = fma2(A0, wA.x, acc[0][0]);
            acc[0][1] = fma2(A0, wA.y, acc[0][1]);
            acc[0][2] = fma2(A0, wB.x, acc[0][2]);
            acc[0][3] = fma2(A0, wB.y, acc[0][3]);
            acc[1][0] = fma2(A1, wA.x, acc[1][0]);
            acc[1][1] = fma2(A1, wA.y, acc[1][1]);
            acc[1][2] = fma2(A1, wB.x, acc[1][2]);
            acc[1][3] = fma2(A1, wB.y, acc[1][3]);
        }
        __syncthreads();
        if (more) {
#pragma unroll
            for (int t = 0; t < 32; t++) As[t * 8 + wid][lane] = r[t];
            Ws[wrow0][wcol0] = wr0;
            Ws[wrow1][wcol1] = wr1;
            __syncthreads();
        }
    }

    // epilogue: scale by norm_src, store 2 nodes x 8 cols
#pragma unroll
    for (int i = 0; i < 2; i++) {
        int n = node0 + nl0 + i;
        if (n < NN) {
            float ns = g_deg_out[n];  // norm_src
            float2 v0 = unpack2(acc[i][0]);
            float2 v1 = unpack2(acc[i][1]);
            float2 v2 = unpack2(acc[i][2]);
            float2 v3 = unpack2(acc[i][3]);
            float4 o0 = make_float4(v0.x * ns, v0.y * ns, v1.x * ns, v1.y * ns);
            float4 o1 = make_float4(v2.x * ns, v2.y * ns, v3.x * ns, v3.y * ns);
            float4* xp = (float4*)(g_x1 + n * 16 + ch * 8);
            xp[0] = o0;
            xp[1] = o1;
        }
    }
}

// ---------------- scatter layer 1: m1[dst] += x1[src] (16 floats) ----------
__global__ void scatter1_kernel() {
    int e = blockIdx.x * blockDim.x + threadIdx.x;
    if (e >= NE) return;
    int s = g_src[e];
    int d = g_dst[e];
    const float4* x = (const float4*)(g_x1 + s * 16);
    float* m = g_m1 + d * 16;
    float4 v0 = x[0], v1 = x[1], v2 = x[2], v3 = x[3];
    red4(m, v0);
    red4(m + 4, v1);
    red4(m + 8, v2);
    red4(m + 12, v3);
}

// ---------------- mid: h = relu(m1*nd + b1); x2 = (h*ns) @ W2 (pad to 8) ---
__global__ void mid_kernel(const float* __restrict__ b1, const float* __restrict__ W2) {
    int n = blockIdx.x * blockDim.x + threadIdx.x;
    if (n >= NN) return;
    float nd = g_deg_in[n];   // norm_dst
    float ns = g_deg_out[n];  // norm_src
    float h[16];
    const float4* mp = (const float4*)(g_m1 + n * 16);
#pragma unroll
    for (int q = 0; q < 4; q++) {
        float4 v = mp[q];
        h[4 * q + 0] = fmaxf(v.x * nd + __ldg(&b1[4 * q + 0]), 0.0f);
        h[4 * q + 1] = fmaxf(v.y * nd + __ldg(&b1[4 * q + 1]), 0.0f);
        h[4 * q + 2] = fmaxf(v.z * nd + __ldg(&b1[4 * q + 2]), 0.0f);
        h[4 * q + 3] = fmaxf(v.w * nd + __ldg(&b1[4 * q + 3]), 0.0f);
    }
    float o[8];
#pragma unroll
    for (int c = 0; c < NO; c++) {
        float s = 0.0f;
#pragma unroll
        for (int j = 0; j < 16; j++) s = fmaf(h[j], __ldg(&W2[j * NO + c]), s);
        o[c] = ns * s;
    }
    o[7] = 0.0f;
    float4* xp = (float4*)(g_x2 + n * 8);
    xp[0] = make_float4(o[0], o[1], o[2], o[3]);
    xp[1] = make_float4(o[4], o[5], o[6], o[7]);
}

// ---------------- scatter layer 2: m2[dst] += x2[src] (8 floats) -----------
__global__ void scatter2_kernel() {
    int e = blockIdx.x * blockDim.x + threadIdx.x;
    if (e >= NE) return;
    int s = g_src[e];
    int d = g_dst[e];
    const float4* x = (const float4*)(g_x2 + s * 8);
    float* m = g_m2 + d * 8;
    float4 v0 = x[0], v1 = x[1];
    red4(m, v0);
    red4(m + 4, v1);
}

// ---------------- output: out = m2*nd + b2 ---------------------------------
__global__ void out_kernel(const float* __restrict__ b2, float* __restrict__ out) {
    int i = blockIdx.x * blockDim.x + threadIdx.x;
    if (i >= NN * NO) return;
    int n = i / NO;
    int c = i - n * NO;
    out[i] = g_m2[n * 8 + c] * g_deg_in[n] + __ldg(&b2[c]);
}

// ---------------- launch ---------------------------------------------------
extern "C" void kernel_launch(void* const* d_in, const int* in_sizes, int n_in,
                              void* d_out, int out_size) {
    const float* feat = (const float*)d_in[0];
    const void* ei    = d_in[1];
    const float* W1   = (const float*)d_in[2];
    const float* b1   = (const float*)d_in[3];
    const float* W2   = (const float*)d_in[4];
    const float* b2   = (const float*)d_in[5];
    float* out        = (float*)d_out;

    void *pdo, *pdi, *pm1, *pm2;
    cudaGetSymbolAddress(&pdo, g_deg_out);
    cudaGetSymbolAddress(&pdi, g_deg_in);
    cudaGetSymbolAddress(&pm1, g_m1);
    cudaGetSymbolAddress(&pm2, g_m2);
    cudaMemsetAsync(pdo, 0, (size_t)NN * sizeof(float));
    cudaMemsetAsync(pdi, 0, (size_t)NN * sizeof(float));
    cudaMemsetAsync(pm1, 0, (size_t)NN * 16 * sizeof(float));
    cudaMemsetAsync(pm2, 0, (size_t)NN * 8 * sizeof(float));

    const int TB = 256;
    const int EBLK = NE / TB;             // 12500 (exact)
    const int NBLK = (NN + TB - 1) / TB;  // 391

    detect_kernel<<<1, 32>>>(ei);
    convert_kernel<<<EBLK, TB>>>(ei);
    deg_kernel<<<EBLK, TB>>>();
    norm_kernel<<<NBLK, TB>>>();
    gemm1_kernel<<<NBLK, TB>>>(feat, W1);
    scatter1_kernel<<<EBLK, TB>>>();
    mid_kernel<<<NBLK, TB>>>(b1, W2);
    scatter2_kernel<<<EBLK, TB>>>();
    out_kernel<<<(NN * NO + TB - 1) / TB, TB>>>(b2, out);
}